// round 1
// baseline (speedup 1.0000x reference)
#include <cuda_runtime.h>
#include <cuda_bf16.h>

// WeightedAverage: out = sum_{3x3} v*exp(-v) / sum_{3x3} exp(-v)
// (softmax(-(local - x^2)) == softmax(-local) since x^2 is constant over the
//  patch axis; zero padding contributes w=1, wv=0.)
//
// Strategy: 64x16 tile + 1 halo in smem. One __expf per loaded element
// (w = exp(-v), wv = w*v), then separable 3x3 box sums:
// per-thread horizontal 3-sums for 6 rows -> 4 vertical outputs.

#define IMG_W 1536
#define IMG_H 1536
#define TX 64
#define TY 16
#define SW 66          // TX + 2 halo
#define SH 18          // TY + 2 halo
#define SSTRIDE 68     // padded row stride (words)

__global__ __launch_bounds__(256, 8)
void wavg_kernel(const float* __restrict__ x, float* __restrict__ out) {
    __shared__ float s_w [SH][SSTRIDE];
    __shared__ float s_wv[SH][SSTRIDE];

    const int bx = blockIdx.x * TX;
    const int by = blockIdx.y * TY;
    const size_t img_off = (size_t)blockIdx.z * (size_t)(IMG_W * IMG_H);
    const float* __restrict__ img  = x   + img_off;
    float*       __restrict__ oimg = out + img_off;

    const int tid = threadIdx.x;

    // Load (TX+2)x(TY+2) halo tile; compute w=exp(-v), wv=w*v once per element.
    #pragma unroll
    for (int i = tid; i < SW * SH; i += 256) {
        const int sy = i / SW;
        const int sx = i - sy * SW;
        const int gx = bx + sx - 1;
        const int gy = by + sy - 1;
        float v = 0.0f;
        if ((unsigned)gx < (unsigned)IMG_W && (unsigned)gy < (unsigned)IMG_H)
            v = __ldg(img + (size_t)gy * IMG_W + gx);
        const float w = __expf(-v);
        s_w [sy][sx] = w;
        s_wv[sy][sx] = w * v;
    }
    __syncthreads();

    // Each thread: column lx, vertical strip of 4 output rows (r0..r0+3).
    const int lx = tid & (TX - 1);
    const int ly = tid >> 6;        // 0..3
    const int r0 = ly * 4;          // tile row of first output pixel

    float hw[6], hwv[6];
    #pragma unroll
    for (int r = 0; r < 6; r++) {
        const int sr = r0 + r;      // smem rows r0 .. r0+5 (tile rows r0-1 .. r0+4)
        hw [r] = s_w [sr][lx] + s_w [sr][lx + 1] + s_w [sr][lx + 2];
        hwv[r] = s_wv[sr][lx] + s_wv[sr][lx + 1] + s_wv[sr][lx + 2];
    }

    const int gx = bx + lx;
    #pragma unroll
    for (int k = 0; k < 4; k++) {
        const float den = hw [k] + hw [k + 1] + hw [k + 2];
        const float num = hwv[k] + hwv[k + 1] + hwv[k + 2];
        oimg[(size_t)(by + r0 + k) * IMG_W + gx] = __fdividef(num, den);
    }
}

extern "C" void kernel_launch(void* const* d_in, const int* in_sizes, int n_in,
                              void* d_out, int out_size) {
    const float* x = (const float*)d_in[0];
    float* out = (float*)d_out;
    dim3 grid(IMG_W / TX, IMG_H / TY, 16);
    wavg_kernel<<<grid, 256>>>(x, out);
}

// round 2
// speedup vs baseline: 1.1109x; 1.1109x over previous
#include <cuda_runtime.h>
#include <cuda_bf16.h>

// WeightedAverage: out = sum_{3x3} v*exp(-v) / sum_{3x3} exp(-v)
// (softmax(-(local - x^2)) == softmax(-local): x^2 is constant over the patch
//  axis. Zero padding contributes w=exp(0)=1 to denominator, 0 to numerator,
//  which is exactly what loading v=0 out-of-bounds produces.)
//
// No shared memory. Each lane owns a float4 (4 columns); warp covers 128 cols.
// Horizontal halo via 2 shfls/row (+ predicated scalar gmem at warp-strip
// edges). Vertical: register ring of horizontal 3-sums over a 16-row sweep,
// one LDG.128 per row per lane, one exp per element, 1-row prefetch.

#define IMG_W 1536
#define IMG_H 1536
#define SROWS 16        // output rows per warp sweep
#define WPB   8         // warps per block

struct Row { float4 v; float vl, vr; };

__device__ __forceinline__ Row load_row(const float* __restrict__ img,
                                        int y, int col0, int lane) {
    Row r;
    r.v = make_float4(0.f, 0.f, 0.f, 0.f);
    r.vl = 0.f; r.vr = 0.f;
    if ((unsigned)y < (unsigned)IMG_H) {             // warp-uniform branch
        r.v = __ldg(reinterpret_cast<const float4*>(img + (size_t)y * IMG_W + col0));
        r.vl = __shfl_up_sync(0xffffffffu,  r.v.w, 1);
        r.vr = __shfl_down_sync(0xffffffffu, r.v.x, 1);
        if (lane == 0)
            r.vl = (col0 > 0) ? __ldg(img + (size_t)y * IMG_W + col0 - 1) : 0.f;
        if (lane == 31)
            r.vr = (col0 + 4 < IMG_W) ? __ldg(img + (size_t)y * IMG_W + col0 + 4) : 0.f;
    }
    return r;
}

__device__ __forceinline__ void hsum(const Row& r, float4& hw, float4& hwv) {
    const float wl = __expf(-r.vl);
    const float w0 = __expf(-r.v.x);
    const float w1 = __expf(-r.v.y);
    const float w2 = __expf(-r.v.z);
    const float w3 = __expf(-r.v.w);
    const float wr = __expf(-r.vr);
    hw.x = wl + w0 + w1;
    hw.y = w0 + w1 + w2;
    hw.z = w1 + w2 + w3;
    hw.w = w2 + w3 + wr;
    const float al = wl * r.vl, a0 = w0 * r.v.x, a1 = w1 * r.v.y;
    const float a2 = w2 * r.v.z, a3 = w3 * r.v.w, ar = wr * r.vr;
    hwv.x = al + a0 + a1;
    hwv.y = a0 + a1 + a2;
    hwv.z = a1 + a2 + a3;
    hwv.w = a2 + a3 + ar;
}

__global__ __launch_bounds__(WPB * 32)
void wavg_kernel(const float* __restrict__ x, float* __restrict__ out) {
    const int lane = threadIdx.x & 31;
    const int wrp  = threadIdx.x >> 5;
    const int col0 = blockIdx.x * 128 + lane * 4;
    const int y0   = (blockIdx.y * WPB + wrp) * SROWS;
    const size_t ibase = (size_t)blockIdx.z * (size_t)(IMG_W * IMG_H);
    const float* __restrict__ img  = x   + ibase;
    float*       __restrict__ oimg = out + ibase;

    float4 hw[3], hwv[3];

    // Prologue: rows y0-1, y0 hsummed; row y0+1 loaded (in flight).
    Row rA = load_row(img, y0 - 1, col0, lane);
    Row rB = load_row(img, y0,     col0, lane);
    hsum(rA, hw[0], hwv[0]);
    Row rC = load_row(img, y0 + 1, col0, lane);
    hsum(rB, hw[1], hwv[1]);

    #pragma unroll
    for (int k = 0; k < SROWS; k++) {
        // Prefetch row y0+k+2 (not needed on the last iteration).
        Row rN;
        if (k < SROWS - 1) {
            rN = load_row(img, y0 + k + 2, col0, lane);
        } else {
            rN.v = make_float4(0.f, 0.f, 0.f, 0.f); rN.vl = 0.f; rN.vr = 0.f;
        }
        // hsum the already-loaded row y0+k+1 into the ring.
        hsum(rC, hw[(k + 2) % 3], hwv[(k + 2) % 3]);
        rC = rN;

        // Output row y0+k from h-sum rows y0+k-1 .. y0+k+1.
        const float4 hw0 = hw[k % 3],  hw1 = hw[(k + 1) % 3],  hw2 = hw[(k + 2) % 3];
        const float4 hv0 = hwv[k % 3], hv1 = hwv[(k + 1) % 3], hv2 = hwv[(k + 2) % 3];
        float4 o;
        o.x = __fdividef(hv0.x + hv1.x + hv2.x, hw0.x + hw1.x + hw2.x);
        o.y = __fdividef(hv0.y + hv1.y + hv2.y, hw0.y + hw1.y + hw2.y);
        o.z = __fdividef(hv0.z + hv1.z + hv2.z, hw0.z + hw1.z + hw2.z);
        o.w = __fdividef(hv0.w + hv1.w + hv2.w, hw0.w + hw1.w + hw2.w);
        *reinterpret_cast<float4*>(oimg + (size_t)(y0 + k) * IMG_W + col0) = o;
    }
}

extern "C" void kernel_launch(void* const* d_in, const int* in_sizes, int n_in,
                              void* d_out, int out_size) {
    const float* x = (const float*)d_in[0];
    float* out = (float*)d_out;
    dim3 grid(IMG_W / 128, IMG_H / (WPB * SROWS), 16);
    wavg_kernel<<<grid, WPB * 32>>>(x, out);
}

// round 3
// speedup vs baseline: 1.2373x; 1.1137x over previous
#include <cuda_runtime.h>
#include <cuda_bf16.h>

// WeightedAverage: out = sum_{3x3} v*exp(-v) / sum_{3x3} exp(-v)
// (softmax(-(local - x^2)) == softmax(-local): x^2 constant over patch axis;
//  zero padding contributes w=1 to denom, 0 to numer == loading v=0 OOB.)
//
// Lane owns float4 (4 cols); warp covers 128 cols, sweeps 24 rows.
// Raw 4-slot register ring, loads issued 3 rows ahead (MLP ~3 rows/warp).
// No shfl: halo columns are 2 scalar LDGs at consume time (L1 hits — the
// neighboring lane's float4 pulled those lines 2 iterations earlier).

#define IMG_W 1536
#define IMG_H 1536
#define SROWS 24
#define WPB   8

__global__ __launch_bounds__(256, 4)
void wavg_kernel(const float* __restrict__ x, float* __restrict__ out) {
    const int lane = threadIdx.x & 31;
    const int wrp  = threadIdx.x >> 5;
    const int col0 = blockIdx.x * 128 + lane * 4;
    const int y0   = (blockIdx.y * WPB + wrp) * SROWS;
    const size_t ibase = (size_t)blockIdx.z * (size_t)(IMG_W * IMG_H);
    const float* __restrict__ img  = x   + ibase;
    float*       __restrict__ oimg = out + ibase;

    const bool has_l = (col0 > 0);
    const bool has_r = (col0 + 4 < IMG_W);

    float4 raw[4];
    float4 hw[3], hwv[3];

    auto load4 = [&](int y) -> float4 {
        if ((unsigned)y < (unsigned)IMG_H)
            return __ldg(reinterpret_cast<const float4*>(img + (size_t)y * IMG_W + col0));
        return make_float4(0.f, 0.f, 0.f, 0.f);
    };

    auto consume = [&](int y, const float4& v, float4& w, float4& wv) {
        float vl = 0.f, vr = 0.f;
        if ((unsigned)y < (unsigned)IMG_H) {
            const float* p = img + (size_t)y * IMG_W + col0;
            if (has_l) vl = __ldg(p - 1);
            if (has_r) vr = __ldg(p + 4);
        }
        const float w0 = __expf(-v.x);
        const float w1 = __expf(-v.y);
        const float w2 = __expf(-v.z);
        const float w3 = __expf(-v.w);
        const float wl = __expf(-vl);
        const float wr = __expf(-vr);
        w.x = wl + w0 + w1;
        w.y = w0 + w1 + w2;
        w.z = w1 + w2 + w3;
        w.w = w2 + w3 + wr;
        const float al = wl * vl,  a0 = w0 * v.x, a1 = w1 * v.y;
        const float a2 = w2 * v.z, a3 = w3 * v.w, ar = wr * vr;
        wv.x = al + a0 + a1;
        wv.y = a0 + a1 + a2;
        wv.z = a1 + a2 + a3;
        wv.w = a2 + a3 + ar;
    };

    // Prologue: slot(row) = (row - y0 + 1) & 3; rows y0-1 .. y0+2 in flight,
    // rows y0-1, y0 consumed (h-slot(row) = (row - y0 + 1) % 3).
    raw[0] = load4(y0 - 1);
    raw[1] = load4(y0);
    raw[2] = load4(y0 + 1);
    raw[3] = load4(y0 + 2);
    consume(y0 - 1, raw[0], hw[0], hwv[0]);
    consume(y0,     raw[1], hw[1], hwv[1]);

    #pragma unroll
    for (int k = 0; k < SROWS; k++) {
        // Prefetch row y0+k+3 into the slot of row y0+k-1 (consumed at k-2).
        if (k < SROWS - 2)
            raw[k & 3] = load4(y0 + k + 3);
        // Consume row y0+k+1 (loaded 3 iterations ago).
        consume(y0 + k + 1, raw[(k + 2) & 3], hw[(k + 2) % 3], hwv[(k + 2) % 3]);

        // Output row y0+k from h-sum rows y0+k-1 .. y0+k+1.
        const float4 w0 = hw [k % 3], w1 = hw [(k + 1) % 3], w2 = hw [(k + 2) % 3];
        const float4 a0 = hwv[k % 3], a1 = hwv[(k + 1) % 3], a2 = hwv[(k + 2) % 3];
        float4 o;
        o.x = __fdividef(a0.x + a1.x + a2.x, w0.x + w1.x + w2.x);
        o.y = __fdividef(a0.y + a1.y + a2.y, w0.y + w1.y + w2.y);
        o.z = __fdividef(a0.z + a1.z + a2.z, w0.z + w1.z + w2.z);
        o.w = __fdividef(a0.w + a1.w + a2.w, w0.w + w1.w + w2.w);
        __stcs(reinterpret_cast<float4*>(oimg + (size_t)(y0 + k) * IMG_W + col0), o);
    }
}

extern "C" void kernel_launch(void* const* d_in, const int* in_sizes, int n_in,
                              void* d_out, int out_size) {
    const float* x = (const float*)d_in[0];
    float* out = (float*)d_out;
    dim3 grid(IMG_W / 128, IMG_H / (WPB * SROWS), 16);
    wavg_kernel<<<grid, WPB * 32>>>(x, out);
}

// round 4
// speedup vs baseline: 1.3036x; 1.0536x over previous
#include <cuda_runtime.h>
#include <cuda_bf16.h>

// WeightedAverage: out = sum_{3x3} v*exp(-v) / sum_{3x3} exp(-v)
// (softmax(-(local - x^2)) == softmax(-local): x^2 constant over patch axis;
//  zero padding contributes w=1 to denom, 0 to numer == loading v=0 OOB.)
//
// Lane owns float4 (4 cols); warp covers 128 cols, sweeps 32 rows.
// Raw 4-slot register ring, loads issued ~2-3 rows ahead.
// Halo columns: 2 scalar LDGs at consume time (L1 hits — neighbor lane's
// float4 pulled those lines 2+ iterations earlier).
// SROWS=32 chosen for wave balance: grid = 12*6*16 = 1152 blocks
// = 1.95 waves of (148 SM x 4 blocks) -> near-zero tail wave.

#define IMG_W 1536
#define IMG_H 1536
#define SROWS 32
#define WPB   8

__global__ __launch_bounds__(256, 4)
void wavg_kernel(const float* __restrict__ x, float* __restrict__ out) {
    const int lane = threadIdx.x & 31;
    const int wrp  = threadIdx.x >> 5;
    const int col0 = blockIdx.x * 128 + lane * 4;
    const int y0   = (blockIdx.y * WPB + wrp) * SROWS;
    const size_t ibase = (size_t)blockIdx.z * (size_t)(IMG_W * IMG_H);
    const float* __restrict__ img  = x   + ibase;
    float*       __restrict__ oimg = out + ibase;

    const bool has_l = (col0 > 0);
    const bool has_r = (col0 + 4 < IMG_W);

    float4 raw[4];
    float4 hw[3], hwv[3];

    auto load4 = [&](int y) -> float4 {
        if ((unsigned)y < (unsigned)IMG_H)
            return __ldg(reinterpret_cast<const float4*>(img + (size_t)y * IMG_W + col0));
        return make_float4(0.f, 0.f, 0.f, 0.f);
    };

    auto consume = [&](int y, const float4& v, float4& w, float4& wv) {
        float vl = 0.f, vr = 0.f;
        if ((unsigned)y < (unsigned)IMG_H) {
            const float* p = img + (size_t)y * IMG_W + col0;
            if (has_l) vl = __ldg(p - 1);
            if (has_r) vr = __ldg(p + 4);
        }
        const float w0 = __expf(-v.x);
        const float w1 = __expf(-v.y);
        const float w2 = __expf(-v.z);
        const float w3 = __expf(-v.w);
        const float wl = __expf(-vl);
        const float wr = __expf(-vr);
        w.x = wl + w0 + w1;
        w.y = w0 + w1 + w2;
        w.z = w1 + w2 + w3;
        w.w = w2 + w3 + wr;
        const float al = wl * vl,  a0 = w0 * v.x, a1 = w1 * v.y;
        const float a2 = w2 * v.z, a3 = w3 * v.w, ar = wr * vr;
        wv.x = al + a0 + a1;
        wv.y = a0 + a1 + a2;
        wv.z = a1 + a2 + a3;
        wv.w = a2 + a3 + ar;
    };

    // Prologue: rows y0-1 .. y0+2 in flight; rows y0-1, y0 consumed.
    raw[0] = load4(y0 - 1);
    raw[1] = load4(y0);
    raw[2] = load4(y0 + 1);
    raw[3] = load4(y0 + 2);
    consume(y0 - 1, raw[0], hw[0], hwv[0]);
    consume(y0,     raw[1], hw[1], hwv[1]);

    #pragma unroll
    for (int k = 0; k < SROWS; k++) {
        // Prefetch row y0+k+3 into the slot freed by row y0+k-1.
        if (k < SROWS - 2)
            raw[k & 3] = load4(y0 + k + 3);
        // Consume row y0+k+1 (loaded 2+ iterations ago).
        consume(y0 + k + 1, raw[(k + 2) & 3], hw[(k + 2) % 3], hwv[(k + 2) % 3]);

        // Output row y0+k from h-sum rows y0+k-1 .. y0+k+1.
        const float4 w0 = hw [k % 3], w1 = hw [(k + 1) % 3], w2 = hw [(k + 2) % 3];
        const float4 a0 = hwv[k % 3], a1 = hwv[(k + 1) % 3], a2 = hwv[(k + 2) % 3];
        float4 o;
        o.x = __fdividef(a0.x + a1.x + a2.x, w0.x + w1.x + w2.x);
        o.y = __fdividef(a0.y + a1.y + a2.y, w0.y + w1.y + w2.y);
        o.z = __fdividef(a0.z + a1.z + a2.z, w0.z + w1.z + w2.z);
        o.w = __fdividef(a0.w + a1.w + a2.w, w0.w + w1.w + w2.w);
        __stcs(reinterpret_cast<float4*>(oimg + (size_t)(y0 + k) * IMG_W + col0), o);
    }
}

extern "C" void kernel_launch(void* const* d_in, const int* in_sizes, int n_in,
                              void* d_out, int out_size) {
    const float* x = (const float*)d_in[0];
    float* out = (float*)d_out;
    dim3 grid(IMG_W / 128, IMG_H / (WPB * SROWS), 16);
    wavg_kernel<<<grid, WPB * 32>>>(x, out);
}